// round 5
// baseline (speedup 1.0000x reference)
#include <cuda_runtime.h>
#include <cstdint>

// Problem constants (fixed by the reference)
#define BATCH    64
#define LSEQ     16384
#define FCH      128
#define KW       16
#define OUT_LEN  16369           // (16384 - 16) + 1
#define TILE_O   64              // output positions per block
#define NTHREADS 256             // 8 warps
#define BO       8               // o positions per inner block
#define XWIN     (BO + KW - 1)   // 23

typedef unsigned long long u64;

// ---------------- packed f32x2 helpers (Blackwell sm_100+) ----------------
__device__ __forceinline__ u64 pack2(float lo, float hi) {
    u64 r;
    asm("mov.b64 %0, {%1, %2};" : "=l"(r) : "f"(lo), "f"(hi));
    return r;
}
__device__ __forceinline__ void ffma2(u64& d, u64 a, u64 b) {
    asm("fma.rn.f32x2 %0, %1, %2, %0;" : "+l"(d) : "l"(a), "l"(b));
}
__device__ __forceinline__ void unpack2(u64 v, float& lo, float& hi) {
    asm("mov.b64 {%0, %1}, %2;" : "=f"(lo), "=f"(hi) : "l"(v));
}

__global__ __launch_bounds__(NTHREADS, 4)
void speccnn1d_kernel(const float* __restrict__ x,
                      const float* __restrict__ kern,
                      float* __restrict__ out) {
    // x window pre-duplicated as {v,v} u64: mainloop is broadcast-LDS.64 -> FFMA2.
    __shared__ u64 xs2[TILE_O + KW];                     // 80 * 8B

    const int tid = threadIdx.x;
    const int b   = blockIdx.y;
    const int o0  = blockIdx.x * TILE_O;

    // ---- stage x window duplicated ----
    {
        const float* xb = x + (size_t)b * LSEQ;
        if (tid < TILE_O + KW - 1) {                     // 79 elements
            int xi = o0 + tid;
            float v = (xi < LSEQ) ? __ldg(&xb[xi]) : 0.0f;
            xs2[tid] = pack2(v, v);
        }
    }

    // Thread -> (channel pair, o-subgroup). og is warp-uniform => broadcast LDS.
    const int f0 = ((tid & 31) << 1) + (((tid >> 5) & 1) << 6);  // even, 0..126
    const int og = tid >> 6;                                     // 0..3

    // ---- hoist this thread's 2 weight rows into 16 packed pairs (32 regs) ----
    u64 w[KW];
    {
        const float4* r0 = reinterpret_cast<const float4*>(kern + (size_t)f0 * KW);
        const float4* r1 = reinterpret_cast<const float4*>(kern + (size_t)(f0 + 1) * KW);
        #pragma unroll
        for (int q = 0; q < 4; q++) {
            float4 a = __ldg(&r0[q]);
            float4 c = __ldg(&r1[q]);
            w[q * 4 + 0] = pack2(a.x, c.x);
            w[q * 4 + 1] = pack2(a.y, c.y);
            w[q * 4 + 2] = pack2(a.z, c.z);
            w[q * 4 + 3] = pack2(a.w, c.w);
        }
    }
    __syncthreads();

    float* outp = out + (size_t)b * OUT_LEN * FCH + f0;

    // ---- two 8-o blocks per thread; diagonal order: each x loaded once ----
    #pragma unroll
    for (int half = 0; half < 2; half++) {
        const int lo = og * (2 * BO) + half * BO;        // local o within tile
        const int o  = o0 + lo;
        const u64* xp = &xs2[lo];                        // base + imm offsets

        u64 acc[BO];
        #pragma unroll
        for (int j = 0; j < BO; j++) acc[j] = 0ull;

        #pragma unroll
        for (int i = 0; i < XWIN; i++) {
            u64 xv = xp[i];                              // single broadcast LDS.64
            #pragma unroll
            for (int j = 0; j < BO; j++) {
                const int k = i - j;
                if (k >= 0 && k < KW)
                    ffma2(acc[j], xv, w[k]);
            }
        }

        float2* po = reinterpret_cast<float2*>(outp + (size_t)o * FCH);
        if (o + BO <= OUT_LEN) {
            // fast path: every tile except the last
            #pragma unroll
            for (int j = 0; j < BO; j++) {
                float lo_, hi_;
                unpack2(acc[j], lo_, hi_);               // pure reg-naming
                float2 r;
                r.x = fmaxf(lo_, 0.0f);
                r.y = fmaxf(hi_, 0.0f);
                po[j * (FCH / 2)] = r;                   // STG.64
            }
        } else {
            #pragma unroll
            for (int j = 0; j < BO; j++) {
                if (o + j < OUT_LEN) {
                    float lo_, hi_;
                    unpack2(acc[j], lo_, hi_);
                    float2 r;
                    r.x = fmaxf(lo_, 0.0f);
                    r.y = fmaxf(hi_, 0.0f);
                    po[j * (FCH / 2)] = r;
                }
            }
        }
    }
}

extern "C" void kernel_launch(void* const* d_in, const int* in_sizes, int n_in,
                              void* d_out, int out_size) {
    const float* x    = (const float*)d_in[0];   // (64, 16384) fp32
    const float* kern = (const float*)d_in[1];   // (128, 16)  fp32
    float* out        = (float*)d_out;           // (64, 16369, 128) fp32

    dim3 grid((OUT_LEN + TILE_O - 1) / TILE_O, BATCH);   // (256, 64)
    speccnn1d_kernel<<<grid, NTHREADS>>>(x, kern, out);
}

// round 6
// speedup vs baseline: 1.2998x; 1.2998x over previous
#include <cuda_runtime.h>
#include <cstdint>

// Problem constants (fixed by the reference)
#define BATCH    64
#define LSEQ     16384
#define FCH      128
#define KW       16
#define OUT_LEN  16369           // (16384 - 16) + 1
#define TILE_O   64              // output positions per block
#define NTHREADS 256             // 8 warps
#define BO       16              // o positions per thread (one block)
#define XWIN     (BO + KW - 1)   // 31

typedef unsigned long long u64;

// ---------------- packed f32x2 helpers (Blackwell sm_100+) ----------------
__device__ __forceinline__ u64 pack2(float lo, float hi) {
    u64 r;
    asm("mov.b64 %0, {%1, %2};" : "=l"(r) : "f"(lo), "f"(hi));
    return r;
}
__device__ __forceinline__ void ffma2(u64& d, u64 a, u64 b) {
    asm("fma.rn.f32x2 %0, %1, %2, %0;" : "+l"(d) : "l"(a), "l"(b));
}
__device__ __forceinline__ void fmul2(u64& d, u64 a, u64 b) {
    asm("mul.rn.f32x2 %0, %1, %2;" : "=l"(d) : "l"(a), "l"(b));
}
__device__ __forceinline__ void unpack2(u64 v, float& lo, float& hi) {
    asm("mov.b64 {%0, %1}, %2;" : "=f"(lo), "=f"(hi) : "l"(v));
}

__global__ __launch_bounds__(NTHREADS, 3)
void speccnn1d_kernel(const float* __restrict__ x,
                      const float* __restrict__ kern,
                      float* __restrict__ out) {
    // x window pre-duplicated as {v,v} u64: mainloop is broadcast-LDS.64 -> FFMA2.
    __shared__ u64 xs2[TILE_O + KW];                     // 80 * 8B

    const int tid = threadIdx.x;
    const int b   = blockIdx.y;
    const int o0  = blockIdx.x * TILE_O;

    // ---- stage x window duplicated ----
    {
        const float* xb = x + (size_t)b * LSEQ;
        if (tid < TILE_O + KW - 1) {                     // 79 elements
            int xi = o0 + tid;
            float v = (xi < LSEQ) ? __ldg(&xb[xi]) : 0.0f;
            xs2[tid] = pack2(v, v);
        }
    }

    // Thread -> (channel pair, o-subgroup). og is warp-uniform => broadcast LDS.
    const int f0 = ((tid & 31) << 1) + (((tid >> 5) & 1) << 6);  // even, 0..126
    const int og = tid >> 6;                                     // 0..3

    // ---- hoist this thread's 2 weight rows into 16 packed pairs (32 regs) ----
    u64 w[KW];
    {
        const float4* r0 = reinterpret_cast<const float4*>(kern + (size_t)f0 * KW);
        const float4* r1 = reinterpret_cast<const float4*>(kern + (size_t)(f0 + 1) * KW);
        #pragma unroll
        for (int q = 0; q < 4; q++) {
            float4 a = __ldg(&r0[q]);
            float4 c = __ldg(&r1[q]);
            w[q * 4 + 0] = pack2(a.x, c.x);
            w[q * 4 + 1] = pack2(a.y, c.y);
            w[q * 4 + 2] = pack2(a.z, c.z);
            w[q * 4 + 3] = pack2(a.w, c.w);
        }
    }
    __syncthreads();

    const int lo = og * BO;                              // local o within tile
    const int o  = o0 + lo;
    const u64* xp = &xs2[lo];                            // base + imm offsets

    // ---- one 16-o block per thread; diagonal order: each x loaded once ----
    u64 acc[BO];

    #pragma unroll
    for (int i = 0; i < XWIN; i++) {
        u64 xv = xp[i];                                  // single broadcast LDS.64
        #pragma unroll
        for (int j = 0; j < BO; j++) {
            const int k = i - j;
            if (k == 0)
                fmul2(acc[j], xv, w[0]);                 // first touch: no init
            else if (k > 0 && k < KW)
                ffma2(acc[j], xv, w[k]);
        }
    }

    float* outp = out + (size_t)b * OUT_LEN * FCH + f0;
    float2* po = reinterpret_cast<float2*>(outp + (size_t)o * FCH);

    if (o + BO <= OUT_LEN) {
        // fast path: every tile except the last
        #pragma unroll
        for (int j = 0; j < BO; j++) {
            float lo_, hi_;
            unpack2(acc[j], lo_, hi_);                   // pure reg-naming
            float2 r;
            r.x = fmaxf(lo_, 0.0f);
            r.y = fmaxf(hi_, 0.0f);
            po[j * (FCH / 2)] = r;                       // STG.64
        }
    } else {
        #pragma unroll
        for (int j = 0; j < BO; j++) {
            if (o + j < OUT_LEN) {
                float lo_, hi_;
                unpack2(acc[j], lo_, hi_);
                float2 r;
                r.x = fmaxf(lo_, 0.0f);
                r.y = fmaxf(hi_, 0.0f);
                po[j * (FCH / 2)] = r;
            }
        }
    }
}

extern "C" void kernel_launch(void* const* d_in, const int* in_sizes, int n_in,
                              void* d_out, int out_size) {
    const float* x    = (const float*)d_in[0];   // (64, 16384) fp32
    const float* kern = (const float*)d_in[1];   // (128, 16)  fp32
    float* out        = (float*)d_out;           // (64, 16369, 128) fp32

    dim3 grid((OUT_LEN + TILE_O - 1) / TILE_O, BATCH);   // (256, 64)
    speccnn1d_kernel<<<grid, NTHREADS>>>(x, kern, out);
}

// round 7
// speedup vs baseline: 1.6026x; 1.2330x over previous
#include <cuda_runtime.h>
#include <cstdint>

#define BATCH    64
#define LSEQ     16384
#define FCH      128
#define KW       16
#define OUT_LEN  16369           // (16384 - 16) + 1
#define TILE_O   128             // o per block
#define NTHREADS 256             // 8 warps
#define WARP_O   16              // o per warp (4 chunks of 4)

typedef unsigned long long u64;

__device__ __forceinline__ u64 pack2(float lo, float hi) {
    u64 r;
    asm("mov.b64 %0, {%1, %2};" : "=l"(r) : "f"(lo), "f"(hi));
    return r;
}
__device__ __forceinline__ void ffma2(u64& d, u64 a, u64 b) {
    asm("fma.rn.f32x2 %0, %1, %2, %0;" : "+l"(d) : "l"(a), "l"(b));
}
__device__ __forceinline__ void fmul2(u64& d, u64 a, u64 b) {
    asm("mul.rn.f32x2 %0, %1, %2;" : "=l"(d) : "l"(a), "l"(b));
}
__device__ __forceinline__ void unpack2(u64 v, float& lo, float& hi) {
    asm("mov.b64 {%0, %1}, %2;" : "=f"(lo), "=f"(hi) : "l"(v));
}

// diagonal step for one output j: first touch is MUL, then FMA
#define DIAG(ACC_A, ACC_B, J)                                   \
    if (i == (J)) { fmul2(ACC_A, xv, w0[0]); fmul2(ACC_B, xv, w1[0]); } \
    else if (i > (J) && i < (J) + KW) {                         \
        ffma2(ACC_A, xv, w0[i - (J)]);                          \
        ffma2(ACC_B, xv, w1[i - (J)]);                          \
    }

__global__ __launch_bounds__(NTHREADS, 2)
void speccnn1d_kernel(const float* __restrict__ x,
                      const float* __restrict__ kern,
                      float* __restrict__ out) {
    // weights pre-paired: ws2[k*64 + fp] = {kern[2fp][k], kern[2fp+1][k]}
    __shared__ __align__(16) u64 ws2[KW * 64];           // 8 KB
    __shared__ u64 xs2[TILE_O + KW];                     // {v,v} duplicated

    const int tid = threadIdx.x;
    const int b   = blockIdx.y;
    const int o0  = blockIdx.x * TILE_O;

    // ---- build paired weights in shared (one-time) ----
    #pragma unroll
    for (int q = 0; q < 4; q++) {
        int idx = tid + q * NTHREADS;                    // 0..1023
        int k  = idx >> 6;
        int fp = idx & 63;
        float lo = __ldg(&kern[(2 * fp)     * KW + k]);
        float hi = __ldg(&kern[(2 * fp + 1) * KW + k]);
        ws2[k * 64 + fp] = pack2(lo, hi);
    }

    // ---- stage x window duplicated ----
    {
        const float* xb = x + (size_t)b * LSEQ;
        if (tid < TILE_O + KW - 1) {                     // 143
            int xi = o0 + tid;
            float v = (xi < LSEQ) ? __ldg(&xb[xi]) : 0.0f;
            xs2[tid] = pack2(v, v);
        }
    }
    __syncthreads();

    const int lane = tid & 31;
    const int warp = tid >> 5;
    const int f0   = lane << 2;                          // 4 channels/thread
    const int fp0  = lane << 1;                          // pair index

    // ---- 16 LDS.128: both weight pairs per k ----
    u64 w0[KW], w1[KW];
    #pragma unroll
    for (int k = 0; k < KW; k++) {
        ulonglong2 ww = *reinterpret_cast<const ulonglong2*>(&ws2[k * 64 + fp0]);
        w0[k] = ww.x;                                    // channels f0, f0+1
        w1[k] = ww.y;                                    // channels f0+2, f0+3
    }

    float* outb = out + (size_t)b * OUT_LEN * FCH;

    // ---- 4 chunks of 4 o; diagonal order, named scalar accumulators ----
    #pragma unroll
    for (int c = 0; c < 4; c++) {
        const int lo_ = warp * WARP_O + c * 4;           // local o
        const int o   = o0 + lo_;
        const u64* xp = &xs2[lo_];

        u64 A0, A1, A2, A3, B0, B1, B2, B3;

        #pragma unroll
        for (int i = 0; i < 4 + KW - 1; i++) {           // 19 broadcast LDS.64
            u64 xv = xp[i];
            DIAG(A0, B0, 0)
            DIAG(A1, B1, 1)
            DIAG(A2, B2, 2)
            DIAG(A3, B3, 3)
        }

        float* po = outb + (size_t)o * FCH + f0;
        float l0, h0, l1, h1;
        float4 r;

        if (o + 4 <= OUT_LEN) {                          // fast path
            unpack2(A0, l0, h0); unpack2(B0, l1, h1);
            r.x = fmaxf(l0, 0.f); r.y = fmaxf(h0, 0.f);
            r.z = fmaxf(l1, 0.f); r.w = fmaxf(h1, 0.f);
            *reinterpret_cast<float4*>(po) = r;

            unpack2(A1, l0, h0); unpack2(B1, l1, h1);
            r.x = fmaxf(l0, 0.f); r.y = fmaxf(h0, 0.f);
            r.z = fmaxf(l1, 0.f); r.w = fmaxf(h1, 0.f);
            *reinterpret_cast<float4*>(po + FCH) = r;

            unpack2(A2, l0, h0); unpack2(B2, l1, h1);
            r.x = fmaxf(l0, 0.f); r.y = fmaxf(h0, 0.f);
            r.z = fmaxf(l1, 0.f); r.w = fmaxf(h1, 0.f);
            *reinterpret_cast<float4*>(po + 2 * FCH) = r;

            unpack2(A3, l0, h0); unpack2(B3, l1, h1);
            r.x = fmaxf(l0, 0.f); r.y = fmaxf(h0, 0.f);
            r.z = fmaxf(l1, 0.f); r.w = fmaxf(h1, 0.f);
            *reinterpret_cast<float4*>(po + 3 * FCH) = r;
        } else {
            if (o < OUT_LEN) {
                unpack2(A0, l0, h0); unpack2(B0, l1, h1);
                r.x = fmaxf(l0, 0.f); r.y = fmaxf(h0, 0.f);
                r.z = fmaxf(l1, 0.f); r.w = fmaxf(h1, 0.f);
                *reinterpret_cast<float4*>(po) = r;
            }
            if (o + 1 < OUT_LEN) {
                unpack2(A1, l0, h0); unpack2(B1, l1, h1);
                r.x = fmaxf(l0, 0.f); r.y = fmaxf(h0, 0.f);
                r.z = fmaxf(l1, 0.f); r.w = fmaxf(h1, 0.f);
                *reinterpret_cast<float4*>(po + FCH) = r;
            }
            if (o + 2 < OUT_LEN) {
                unpack2(A2, l0, h0); unpack2(B2, l1, h1);
                r.x = fmaxf(l0, 0.f); r.y = fmaxf(h0, 0.f);
                r.z = fmaxf(l1, 0.f); r.w = fmaxf(h1, 0.f);
                *reinterpret_cast<float4*>(po + 2 * FCH) = r;
            }
            if (o + 3 < OUT_LEN) {
                unpack2(A3, l0, h0); unpack2(B3, l1, h1);
                r.x = fmaxf(l0, 0.f); r.y = fmaxf(h0, 0.f);
                r.z = fmaxf(l1, 0.f); r.w = fmaxf(h1, 0.f);
                *reinterpret_cast<float4*>(po + 3 * FCH) = r;
            }
        }
    }
}

extern "C" void kernel_launch(void* const* d_in, const int* in_sizes, int n_in,
                              void* d_out, int out_size) {
    const float* x    = (const float*)d_in[0];   // (64, 16384) fp32
    const float* kern = (const float*)d_in[1];   // (128, 16)  fp32
    float* out        = (float*)d_out;           // (64, 16369, 128) fp32

    dim3 grid((OUT_LEN + TILE_O - 1) / TILE_O, BATCH);   // (128, 64)
    speccnn1d_kernel<<<grid, NTHREADS>>>(x, kern, out);
}